// round 1
// baseline (speedup 1.0000x reference)
#include <cuda_runtime.h>

#define N_NODES 50000
#define N_EDGES 800000
#define CH 64
#define CH4 (CH / 4)          // 16 float4 per row
#define OUT_ELEMS (N_NODES * CH)

// ---- scratch (device globals; no allocation allowed) ----
__device__ float g_w_mean[CH * CH];
__device__ float g_w_var[CH * CH];
__device__ float g_sup_mean[OUT_ELEMS];
__device__ float g_sup_var[OUT_ELEMS];

// ---------------------------------------------------------------------------
// Kernel 0: zero the two accumulation regions of d_out (poisoned to 0xAA).
// 6,400,000 floats = 1,600,000 float4.
// ---------------------------------------------------------------------------
__global__ __launch_bounds__(256) void zero_kernel(float4* out4) {
    int i = blockIdx.x * 256 + threadIdx.x;
    if (i < OUT_ELEMS * 2 / 4) {
        out4[i] = make_float4(0.f, 0.f, 0.f, 0.f);
    }
}

// ---------------------------------------------------------------------------
// Kernel 1: build reparameterized weights + KL sum (single block).
// ---------------------------------------------------------------------------
__global__ __launch_bounds__(256) void prep_kernel(
    const float* __restrict__ mu_m, const float* __restrict__ ls_m,
    const float* __restrict__ eps_m,
    const float* __restrict__ mu_s, const float* __restrict__ ls_s,
    const float* __restrict__ eps_s,
    float* __restrict__ kl_out)
{
    __shared__ float red[256];
    int tid = threadIdx.x;
    float acc = 0.f;
    for (int i = tid; i < CH * CH; i += 256) {
        float lm = ls_m[i], mm = mu_m[i];
        g_w_mean[i] = mm + eps_m[i] * expf(lm);
        acc += 0.5f * (expf(2.f * lm) + mm * mm - 2.f * lm - 1.f);
        float lv = ls_s[i], ms = mu_s[i];
        g_w_var[i] = ms + eps_s[i] * expf(lv);
        acc += 0.5f * (expf(2.f * lv) + ms * ms - 2.f * lv - 1.f);
    }
    red[tid] = acc;
    __syncthreads();
    for (int s = 128; s > 0; s >>= 1) {
        if (tid < s) red[tid] += red[tid + s];
        __syncthreads();
    }
    if (tid == 0) kl_out[0] = red[0];
}

// ---------------------------------------------------------------------------
// Kernel 2: fused dual GEMM.
//   sup_mean = mean @ W_mean        [50000, 64]
//   sup_var  = (std*std) @ W_var    [50000, 64]
// 16 rows per block, 256 threads, weights staged in shared.
// ---------------------------------------------------------------------------
__global__ __launch_bounds__(256) void gemm_kernel(
    const float* __restrict__ mean, const float* __restrict__ stdv)
{
    __shared__ float sWm[CH * CH];
    __shared__ float sWv[CH * CH];
    __shared__ float sXm[16 * CH];
    __shared__ float sXv[16 * CH];

    int tid = threadIdx.x;

    // stage weights (4096 floats each -> 1024 float4 each)
    for (int i = tid; i < CH * CH / 4; i += 256) {
        ((float4*)sWm)[i] = ((const float4*)g_w_mean)[i];
        ((float4*)sWv)[i] = ((const float4*)g_w_var)[i];
    }

    // stage 16-row input tiles (16*16 = 256 float4 per tensor -> one per thread)
    int row0 = blockIdx.x * 16;
    {
        int r = tid >> 4;          // 0..15
        int c4 = tid & 15;         // 0..15
        int node = row0 + r;
        float4 m = ((const float4*)mean)[node * CH4 + c4];
        float4 s = ((const float4*)stdv)[node * CH4 + c4];
        ((float4*)sXm)[r * CH4 + c4] = m;
        ((float4*)sXv)[r * CH4 + c4] =
            make_float4(s.x * s.x, s.y * s.y, s.z * s.z, s.w * s.w);
    }
    __syncthreads();

    int c  = tid & 63;     // output column
    int rg = tid >> 6;     // 0..3  (row group)
    #pragma unroll
    for (int rr = 0; rr < 4; rr++) {
        int r = rg * 4 + rr;
        int node = row0 + r;
        float am = 0.f, av = 0.f;
        #pragma unroll
        for (int k = 0; k < CH; k++) {
            am = fmaf(sXm[r * CH + k], sWm[k * CH + c], am);
            av = fmaf(sXv[r * CH + k], sWv[k * CH + c], av);
        }
        g_sup_mean[node * CH + c] = am;
        g_sup_var [node * CH + c] = av;
    }
}

// ---------------------------------------------------------------------------
// Kernel 3: edge scatter for BOTH branches.
// One thread per (edge, float4-chunk) pair; 16 consecutive lanes cover one
// edge => fully coalesced 256B gather per edge, vector reductions on scatter.
// ---------------------------------------------------------------------------
__global__ __launch_bounds__(256) void scatter_kernel(
    const int* __restrict__ ei, const float* __restrict__ ew,
    float* __restrict__ out_mean, float* __restrict__ out_var)
{
    int idx = blockIdx.x * 256 + threadIdx.x;          // < 2*N_EDGES*16 = 25.6M
    int j = idx & 15;                                  // chunk within row
    int t = idx >> 4;                                  // branch*N_EDGES + edge
    int branch = (t >= N_EDGES) ? 1 : 0;
    int e = t - branch * N_EDGES;

    int src = __ldg(&ei[e]);
    int dst = __ldg(&ei[N_EDGES + e]);
    float w = __ldg(&ew[e]);

    const float4* sup;
    float* outp;
    if (branch) {
        w *= w;
        sup = (const float4*)g_sup_var;
        outp = out_var;
    } else {
        sup = (const float4*)g_sup_mean;
        outp = out_mean;
    }

    float4 v = __ldg(&sup[src * CH4 + j]);
    float4 m = make_float4(v.x * w, v.y * w, v.z * w, v.w * w);
    float* addr = outp + dst * CH + j * 4;
    asm volatile("red.global.add.v4.f32 [%0], {%1, %2, %3, %4};"
                 :: "l"(addr), "f"(m.x), "f"(m.y), "f"(m.z), "f"(m.w)
                 : "memory");
}

// ---------------------------------------------------------------------------
// Kernel 4: finalize std branch: std = sqrt(exp(log_var) + 1e-6), in place.
// ---------------------------------------------------------------------------
__global__ __launch_bounds__(256) void finalize_kernel(float4* __restrict__ out_var4) {
    int i = blockIdx.x * 256 + threadIdx.x;
    if (i < OUT_ELEMS / 4) {
        float4 x = out_var4[i];
        x.x = sqrtf(expf(x.x) + 1e-6f);
        x.y = sqrtf(expf(x.y) + 1e-6f);
        x.z = sqrtf(expf(x.z) + 1e-6f);
        x.w = sqrtf(expf(x.w) + 1e-6f);
        out_var4[i] = x;
    }
}

// ---------------------------------------------------------------------------
extern "C" void kernel_launch(void* const* d_in, const int* in_sizes, int n_in,
                              void* d_out, int out_size)
{
    const float* mean  = (const float*)d_in[0];   // [50000, 64]
    const float* stdv  = (const float*)d_in[1];   // [50000, 64]
    const int*   ei    = (const int*)  d_in[2];   // [2, 800000]
    const float* ew    = (const float*)d_in[3];   // [800000]
    const float* mu_m  = (const float*)d_in[4];
    const float* ls_m  = (const float*)d_in[5];
    const float* eps_m = (const float*)d_in[6];
    const float* mu_s  = (const float*)d_in[7];
    const float* ls_s  = (const float*)d_in[8];
    const float* eps_s = (const float*)d_in[9];

    float* out_mean = (float*)d_out;                   // [50000*64]
    float* out_var  = out_mean + OUT_ELEMS;            // [50000*64] (log-var -> std)
    float* kl_out   = out_mean + 2 * OUT_ELEMS;        // scalar

    // 1) zero accumulation regions
    {
        int n4 = OUT_ELEMS * 2 / 4;
        zero_kernel<<<(n4 + 255) / 256, 256>>>((float4*)d_out);
    }
    // 2) weights + KL
    prep_kernel<<<1, 256>>>(mu_m, ls_m, eps_m, mu_s, ls_s, eps_s, kl_out);
    // 3) dual GEMM -> support tensors
    gemm_kernel<<<N_NODES / 16, 256>>>(mean, stdv);
    // 4) edge scatter (both branches)
    {
        int total = 2 * N_EDGES * 16;                  // 25,600,000
        scatter_kernel<<<total / 256, 256>>>(ei, ew, out_mean, out_var);
    }
    // 5) finalize std
    {
        int n4 = OUT_ELEMS / 4;
        finalize_kernel<<<(n4 + 255) / 256, 256>>>((float4*)out_var);
    }
}